// round 2
// baseline (speedup 1.0000x reference)
#include <cuda_runtime.h>

#define N_NODES 262144
#define C 64
#define K 16
#define NCLS 40

#define WARPS 16
#define NODES_PER_WARP 8
#define NODES_PER_BLOCK (WARPS * NODES_PER_WARP)   // 128
#define FSTRIDE 132   // 128 feat floats + 4 pad -> conflict-free phase-2 reads

// smem plan (dynamic): [0,5120) fused W (interleaved float4 layout),
// [5120,5160) fused bias, [5168, 5168+16*8*132) feat
#define SW_FLOATS 5120
#define SBF_OFF   5120
#define SFEAT_OFF 5168
#define SMEM_FLOATS (SFEAT_OFF + WARPS * NODES_PER_WARP * FSTRIDE)   // 22064
#define SMEM_BYTES  (SMEM_FLOATS * 4)                                // 88256

// scratch (allocation-free rule: __device__ globals)
__device__ __align__(256) static float d_h[N_NODES * C];   // 64 MB, L2-resident working set
__device__ __align__(16)  static float d_W[2 * C * NCLS];  // fused weights, interleaved layout
__device__ static float d_bf[NCLS];                        // fused bias
__device__ static int   d_idx64;                           // nbr_idx dtype flag

// ---------- packed f32x2 helpers (FFMA2) ----------
__device__ __forceinline__ unsigned long long pack2(float a, float b) {
    unsigned long long r;
    asm("mov.b64 %0, {%1,%2};" : "=l"(r) : "f"(a), "f"(b));
    return r;
}
__device__ __forceinline__ void unpack2(unsigned long long v, float& a, float& b) {
    asm("mov.b64 {%0,%1}, %2;" : "=f"(a), "=f"(b) : "l"(v));
}
__device__ __forceinline__ void ffma2(unsigned long long& d, unsigned long long a,
                                      unsigned long long b) {
    asm("fma.rn.f32x2 %0, %1, %2, %0;" : "+l"(d) : "l"(a), "l"(b));
}

// ---------- kernel 0: detect whether nbr_idx is int64 or int32 ----------
__global__ void detect_idx_kernel(const unsigned int* __restrict__ w) {
    __shared__ int any;
    if (threadIdx.x == 0) any = 0;
    __syncthreads();
    if (w[2 * threadIdx.x + 1] != 0u) any = 1;
    __syncthreads();
    if (threadIdx.x == 0) d_idx64 = (any ? 0 : 1);
}

// ---------- kernel 1: CPE depthwise conv (kernel 3 over node dim) + residual ----------
// Rolling window: each thread owns one channel-quad q and 8 consecutive nodes.
__global__ void cpe_kernel(const float4* __restrict__ x4,
                           const float* __restrict__ cw,   // [C,3]
                           const float* __restrict__ cb) { // [C]
    const int idx = blockIdx.x * blockDim.x + threadIdx.x;
    const int q = idx & 15;
    const int n0 = (idx >> 4) * 8;
    if (n0 >= N_NODES) return;
    const int c0 = q * 4;

    const float w0x = __ldg(cw + (c0 + 0) * 3 + 0), w1x = __ldg(cw + (c0 + 0) * 3 + 1), w2x = __ldg(cw + (c0 + 0) * 3 + 2);
    const float w0y = __ldg(cw + (c0 + 1) * 3 + 0), w1y = __ldg(cw + (c0 + 1) * 3 + 1), w2y = __ldg(cw + (c0 + 1) * 3 + 2);
    const float w0z = __ldg(cw + (c0 + 2) * 3 + 0), w1z = __ldg(cw + (c0 + 2) * 3 + 1), w2z = __ldg(cw + (c0 + 2) * 3 + 2);
    const float w0w = __ldg(cw + (c0 + 3) * 3 + 0), w1w = __ldg(cw + (c0 + 3) * 3 + 1), w2w = __ldg(cw + (c0 + 3) * 3 + 2);
    const float bx = __ldg(cb + c0 + 0), by = __ldg(cb + c0 + 1), bz = __ldg(cb + c0 + 2), bw = __ldg(cb + c0 + 3);

    const float4 zero = make_float4(0.f, 0.f, 0.f, 0.f);
    float4 a = (n0 > 0) ? x4[(n0 - 1) * 16 + q] : zero;
    float4 b = x4[n0 * 16 + q];
    float4* h4 = reinterpret_cast<float4*>(d_h);
    #pragma unroll
    for (int r = 0; r < 8; ++r) {
        const int n = n0 + r;
        const float4 nx = (n + 1 < N_NODES) ? x4[(n + 1) * 16 + q] : zero;
        float4 o;
        o.x = b.x + (a.x * w0x + b.x * w1x + nx.x * w2x + bx);
        o.y = b.y + (a.y * w0y + b.y * w1y + nx.y * w2y + by);
        o.z = b.z + (a.z * w0z + b.z * w1z + nx.z * w2z + bz);
        o.w = b.w + (a.w * w0w + b.w * w1w + nx.w * w2w + bw);
        h4[n * 16 + q] = o;
        a = b; b = nx;
    }
}

// ---------- kernel 2: fuse grapher projection into the classifier head ----------
// Writes W in interleaved layout for dense LDS.128 reads:
//   float4 unit index (cp*20 + t*4 + pg), comps:
//     0: W[2cp][pg*10+2t]   1: W[2cp][pg*10+2t+1]
//     2: W[2cp+1][pg*10+2t] 3: W[2cp+1][pg*10+2t+1]
__global__ void fuse_w_kernel(const float* __restrict__ gw,  // [128,64]
                              const float* __restrict__ gb,  // [64]
                              const float* __restrict__ ow,  // [64,40]
                              const float* __restrict__ ob) {// [40]
    int t = blockIdx.x * blockDim.x + threadIdx.x;
    if (t < 2 * C * NCLS) {
        int c = t / NCLS, j = t % NCLS;
        float acc = (c < C) ? ow[c * NCLS + j] : 0.f;
        #pragma unroll 8
        for (int d = 0; d < C; ++d) acc += gw[c * C + d] * ow[d * NCLS + j];
        const int cp = c >> 1, r = c & 1;
        const int pg = j / 10, u = j - 10 * pg;
        const int tt = u >> 1, comp = r * 2 + (u & 1);
        d_W[(cp * 20 + tt * 4 + pg) * 4 + comp] = acc;
    } else if (t < 2 * C * NCLS + NCLS) {
        int j = t - 2 * C * NCLS;
        float acc = ob[j];
        for (int d = 0; d < C; ++d) acc += gb[d] * ow[d * NCLS + j];
        d_bf[j] = acc;
    }
}

// ---------- kernel 3: gather + max-relative + fused GEMM + log_softmax ----------
__global__ __launch_bounds__(WARPS * 32, 2) void main_kernel(const void* __restrict__ nbr,
                                                             float* __restrict__ out) {
    extern __shared__ float smem[];
    float* sW   = smem;
    float* sBF  = smem + SBF_OFF;
    float* sFeatAll = smem + SFEAT_OFF;

    const float* __restrict__ H = d_h;
    const int tid = threadIdx.x;

    // stage fused weights into shared (float4), overlapped with phase-1 gather
    {
        float4* dst = reinterpret_cast<float4*>(sW);
        const float4* src = reinterpret_cast<const float4*>(d_W);
        for (int i = tid; i < SW_FLOATS / 4; i += WARPS * 32) dst[i] = src[i];
        if (tid < NCLS) sBF[tid] = d_bf[tid];
    }

    const int warp = tid >> 5, lane = tid & 31;
    const int nodeBase = blockIdx.x * NODES_PER_BLOCK + warp * NODES_PER_WARP;
    float* feat = sFeatAll + warp * NODES_PER_WARP * FSTRIDE;
    const int is64 = d_idx64;

    // ---- phase 1: gather 16 neighbors per node, running channel-wise max ----
    // lane owns channels (2*lane, 2*lane+1) as float2
    #pragma unroll 1
    for (int i = 0; i < NODES_PER_WARP; ++i) {
        const int n = nodeBase + i;
        int myj = 0;
        if (lane < K) {
            if (is64) myj = (int)((const long long*)nbr)[(size_t)n * K + lane];
            else      myj = ((const int*)nbr)[n * K + lane];
        }
        const float2 hv = *(const float2*)(H + n * C + 2 * lane);
        float2 mv = make_float2(-3.402823466e38f, -3.402823466e38f);
        #pragma unroll
        for (int k = 0; k < K; ++k) {
            const int j = __shfl_sync(0xffffffffu, myj, k);
            const float2 xv = __ldg((const float2*)(H + j * C + 2 * lane));
            mv.x = fmaxf(mv.x, xv.x);
            mv.y = fmaxf(mv.y, xv.y);
        }
        *(float2*)(feat + i * FSTRIDE + 2 * lane) = hv;                 // feat[0:64)  = h
        float2 rv = make_float2(mv.x - hv.x, mv.y - hv.y);              // max(xj)-h == max(xj-h)
        *(float2*)(feat + i * FSTRIDE + C + 2 * lane) = rv;             // feat[64:128) = rel
    }
    __syncthreads();  // weight staging + feat visibility

    // ---- phase 2: per-node [1,128] @ [128,40], dense LDS.128 weights + FFMA2 ----
    // lane -> (node ng = lane>>2, class-group pg = lane&3); classes pg*10 .. pg*10+9
    const int ng = lane >> 2, pg = lane & 3;
    const float* fv = feat + ng * FSTRIDE;
    const ulonglong2* sWu2 = reinterpret_cast<const ulonglong2*>(sW);

    unsigned long long acc[5];
    #pragma unroll
    for (int t = 0; t < 5; ++t) {
        const int p = pg * 5 + t;
        acc[t] = pack2(sBF[2 * p], sBF[2 * p + 1]);
    }
    #pragma unroll 8
    for (int cp = 0; cp < C; ++cp) {   // c-pair over the 128 feat channels
        const float2 v = *(const float2*)(fv + 2 * cp);
        const unsigned long long vx = pack2(v.x, v.x);
        const unsigned long long vy = pack2(v.y, v.y);
        const ulonglong2* wrow = sWu2 + cp * 20 + pg;
        #pragma unroll
        for (int t = 0; t < 5; ++t) {
            const ulonglong2 w = wrow[t * 4];
            ffma2(acc[t], vx, w.x);
            ffma2(acc[t], vy, w.y);
        }
    }

    // ---- log_softmax over 40 classes (reduce across the 4 lanes of each node) ----
    float lg[10];
    #pragma unroll
    for (int t = 0; t < 5; ++t) unpack2(acc[t], lg[2 * t], lg[2 * t + 1]);
    float m = lg[0];
    #pragma unroll
    for (int i = 1; i < 10; ++i) m = fmaxf(m, lg[i]);
    m = fmaxf(m, __shfl_xor_sync(0xffffffffu, m, 1));
    m = fmaxf(m, __shfl_xor_sync(0xffffffffu, m, 2));
    float s = 0.f;
    #pragma unroll
    for (int i = 0; i < 10; ++i) s += __expf(lg[i] - m);
    s += __shfl_xor_sync(0xffffffffu, s, 1);
    s += __shfl_xor_sync(0xffffffffu, s, 2);
    const float lse = m + __logf(s);

    const int n = nodeBase + ng;
    float* op = out + (size_t)n * NCLS + pg * 10;
    #pragma unroll
    for (int t = 0; t < 5; ++t) {
        float2 o;
        o.x = lg[2 * t]     - lse;
        o.y = lg[2 * t + 1] - lse;
        *(float2*)(op + 2 * t) = o;
    }
}

extern "C" void kernel_launch(void* const* d_in, const int* in_sizes, int n_in,
                              void* d_out, int out_size) {
    const float* x  = (const float*)d_in[0];
    const void*  nb = d_in[1];
    const float* cw = (const float*)d_in[2];
    const float* cb = (const float*)d_in[3];
    const float* gw = (const float*)d_in[4];
    const float* gb = (const float*)d_in[5];
    const float* ow = (const float*)d_in[6];
    const float* ob = (const float*)d_in[7];
    float* out = (float*)d_out;

    static int attr_done = 0;
    if (!attr_done) {
        cudaFuncSetAttribute(main_kernel, cudaFuncAttributeMaxDynamicSharedMemorySize, SMEM_BYTES);
        attr_done = 1;
    }

    detect_idx_kernel<<<1, 256>>>((const unsigned int*)nb);
    cpe_kernel<<<(N_NODES / 8 * 16 + 255) / 256, 256>>>((const float4*)x, cw, cb);
    fuse_w_kernel<<<(2 * C * NCLS + NCLS + 127) / 128, 128>>>(gw, gb, ow, ob);
    main_kernel<<<N_NODES / NODES_PER_BLOCK, WARPS * 32, SMEM_BYTES>>>(nb, out);
}

// round 4
// speedup vs baseline: 1.8662x; 1.8662x over previous
#include <cuda_runtime.h>
#include <cuda_bf16.h>
#include <cstdint>

#define N_NODES 262144
#define C 64
#define K 16
#define NCLS 40

#define WARPS 16
#define THREADS (WARPS * 32)
#define NODES_PER_BLOCK 128
#define NODES_PER_WARP 8

// ---- A-fragment feat storage: 16 ktiles, each 128 rows x 8 cols bf16 = 2048B, pad to 2064 ----
#define KTS 2064
#define F_SPLIT (16 * KTS)          // 33024 bytes per split (hi / lo)

// ---- dynamic smem layout (bytes) ----
#define SM_F_HI 0
#define SM_F_LO 33024
#define SM_B    66048               // B frag images: hi (10240) then lo (10240)
#define SM_BIAS 86528               // 40 floats
#define SMEM_BYTES 86688

#define B_IMG_U16 5120              // one image = 16kt*5nt*32lane uint32 = 5120 uint16

// ---- device scratch (allocation-free rule) ----
__device__ __align__(256) static float d_h[N_NODES * C];       // 64 MB
__device__ static float d_bf[NCLS];                            // fused bias
__device__ __align__(16) static uint16_t d_Bfrag[2 * B_IMG_U16]; // pre-packed B fragments hi|lo
__device__ static int d_idx64;

// ---------- helpers ----------
__device__ __forceinline__ uint32_t pack_bf2(float a, float b, float& ra, float& rb) {
    __nv_bfloat162 t = __floats2bfloat162_rn(a, b);
    ra = a - __bfloat162float(__low2bfloat16(t));
    rb = b - __bfloat162float(__high2bfloat16(t));
    return *reinterpret_cast<uint32_t*>(&t);
}
__device__ __forceinline__ uint32_t pack_bf2n(float a, float b) {
    __nv_bfloat162 t = __floats2bfloat162_rn(a, b);
    return *reinterpret_cast<uint32_t*>(&t);
}
__device__ __forceinline__ void mma_bf16(float* c, uint32_t a0, uint32_t a1, uint32_t b) {
    asm volatile("mma.sync.aligned.m16n8k8.row.col.f32.bf16.bf16.f32 "
                 "{%0,%1,%2,%3}, {%4,%5}, {%6}, {%0,%1,%2,%3};"
                 : "+f"(c[0]), "+f"(c[1]), "+f"(c[2]), "+f"(c[3])
                 : "r"(a0), "r"(a1), "r"(b));
}

// ---------- kernel 0: idx dtype detect ----------
__global__ void detect_idx_kernel(const unsigned int* __restrict__ w) {
    __shared__ int any;
    if (threadIdx.x == 0) any = 0;
    __syncthreads();
    if (w[2 * threadIdx.x + 1] != 0u) any = 1;
    __syncthreads();
    if (threadIdx.x == 0) d_idx64 = (any ? 0 : 1);
}

// ---------- kernel 1: CPE depthwise conv + residual ----------
__global__ void cpe_kernel(const float4* __restrict__ x4,
                           const float* __restrict__ cw,
                           const float* __restrict__ cb) {
    const int idx = blockIdx.x * blockDim.x + threadIdx.x;
    const int q = idx & 15;
    const int n0 = (idx >> 4) * 8;
    if (n0 >= N_NODES) return;
    const int c0 = q * 4;
    const float w0x = __ldg(cw + (c0+0)*3+0), w1x = __ldg(cw + (c0+0)*3+1), w2x = __ldg(cw + (c0+0)*3+2);
    const float w0y = __ldg(cw + (c0+1)*3+0), w1y = __ldg(cw + (c0+1)*3+1), w2y = __ldg(cw + (c0+1)*3+2);
    const float w0z = __ldg(cw + (c0+2)*3+0), w1z = __ldg(cw + (c0+2)*3+1), w2z = __ldg(cw + (c0+2)*3+2);
    const float w0w = __ldg(cw + (c0+3)*3+0), w1w = __ldg(cw + (c0+3)*3+1), w2w = __ldg(cw + (c0+3)*3+2);
    const float bx = __ldg(cb+c0+0), by = __ldg(cb+c0+1), bz = __ldg(cb+c0+2), bw = __ldg(cb+c0+3);

    const float4 zero = make_float4(0.f, 0.f, 0.f, 0.f);
    float4 a = (n0 > 0) ? x4[(n0 - 1) * 16 + q] : zero;
    float4 b = x4[n0 * 16 + q];
    float4* h4 = reinterpret_cast<float4*>(d_h);
    #pragma unroll
    for (int r = 0; r < 8; ++r) {
        const int n = n0 + r;
        const float4 nx = (n + 1 < N_NODES) ? x4[(n + 1) * 16 + q] : zero;
        float4 o;
        o.x = b.x + (a.x*w0x + b.x*w1x + nx.x*w2x + bx);
        o.y = b.y + (a.y*w0y + b.y*w1y + nx.y*w2y + by);
        o.z = b.z + (a.z*w0z + b.z*w1z + nx.z*w2z + bz);
        o.w = b.w + (a.w*w0w + b.w*w1w + nx.w*w2w + bw);
        h4[n * 16 + q] = o;
        a = b; b = nx;
    }
}

// ---------- kernel 2: fuse grapher into head; emit B-fragment images (hi/lo bf16) ----------
// W[c][j] = (c<64 ? ow[c][j] : 0) + sum_d gw[c][d]*ow[d][j];  B[k=c][n=j]
// m16n8k8 B frag: lane = (j&7)*4 + ((c&7)>>1), half = c&1
__global__ void fuse_w_kernel(const float* __restrict__ gw, const float* __restrict__ gb,
                              const float* __restrict__ ow, const float* __restrict__ ob) {
    int t = blockIdx.x * blockDim.x + threadIdx.x;
    if (t < 2 * C * NCLS) {
        int c = t / NCLS, j = t % NCLS;
        float acc = (c < C) ? ow[c * NCLS + j] : 0.f;
        #pragma unroll 8
        for (int d = 0; d < C; ++d) acc += gw[c * C + d] * ow[d * NCLS + j];
        const int kt = c >> 3, nt = j >> 3;
        const int lane = (j & 7) * 4 + ((c & 7) >> 1);
        const int half = c & 1;
        const int idx = ((kt * 5 + nt) * 32 + lane) * 2 + half;
        __nv_bfloat16 hi = __float2bfloat16(acc);
        __nv_bfloat16 lo = __float2bfloat16(acc - __bfloat162float(hi));
        d_Bfrag[idx]             = *reinterpret_cast<uint16_t*>(&hi);
        d_Bfrag[idx + B_IMG_U16] = *reinterpret_cast<uint16_t*>(&lo);
    } else if (t < 2 * C * NCLS + NCLS) {
        int j = t - 2 * C * NCLS;
        float acc = ob[j];
        for (int d = 0; d < C; ++d) acc += gb[d] * ow[d * NCLS + j];
        d_bf[j] = acc;
    }
}

// ---------- kernel 3: gather -> A-frag tiles -> mma.sync bf16 -> log_softmax ----------
__global__ __launch_bounds__(THREADS, 2) void main_kernel(const void* __restrict__ nbr,
                                                          float* __restrict__ out) {
    extern __shared__ __align__(16) char smem[];
    const int tid = threadIdx.x;
    const int warp = tid >> 5, lane = tid & 31;
    const float* __restrict__ H = d_h;

    // stage B fragment images (20480 B) + bias
    {
        const int4* src = reinterpret_cast<const int4*>(d_Bfrag);
        int4* dst = reinterpret_cast<int4*>(smem + SM_B);
        #pragma unroll
        for (int i = tid; i < 20480 / 16; i += THREADS) dst[i] = src[i];
        if (tid < NCLS) *(float*)(smem + SM_BIAS + 4 * tid) = d_bf[tid];
    }

    // ---- gather: 16 warps x 8 nodes; lane owns channel pair (2l, 2l+1) ----
    const int nodeBase = blockIdx.x * NODES_PER_BLOCK + warp * NODES_PER_WARP;
    const int is64 = d_idx64;
    #pragma unroll 1
    for (int i = 0; i < NODES_PER_WARP; ++i) {
        const int n = nodeBase + i;
        int myj = 0;
        if (lane < K) {
            if (is64) myj = (int)((const long long*)nbr)[(size_t)n * K + lane];
            else      myj = ((const int*)nbr)[n * K + lane];
        }
        const float2 hv = *(const float2*)(H + n * C + 2 * lane);
        float2 mv = make_float2(-3.402823466e38f, -3.402823466e38f);
        #pragma unroll
        for (int k = 0; k < K; ++k) {
            const int j = __shfl_sync(0xffffffffu, myj, k);
            const float2 xv = __ldg((const float2*)(H + j * C + 2 * lane));
            mv.x = fmaxf(mv.x, xv.x);
            mv.y = fmaxf(mv.y, xv.y);
        }
        const float2 rv = make_float2(mv.x - hv.x, mv.y - hv.y);  // max(xj)-h == max(xj-h)

        // write A-fragment layout: base = kt*KTS + slot*128 + lane'*4
        const int nl = warp * NODES_PER_WARP + i;                 // block-local node 0..127
        const uint32_t base = (uint32_t)(lane >> 2) * KTS
                            + (uint32_t)((nl >> 4) * 2 + ((nl >> 3) & 1)) * 128
                            + (uint32_t)((nl & 7) * 4 + (lane & 3)) * 4;
        float hlx, hly, rlx, rly;
        const uint32_t hHi = pack_bf2(hv.x, hv.y, hlx, hly);
        const uint32_t rHi = pack_bf2(rv.x, rv.y, rlx, rly);
        *(uint32_t*)(smem + SM_F_HI + base)             = hHi;           // ktiles 0..7 (h)
        *(uint32_t*)(smem + SM_F_HI + 8 * KTS + base)   = rHi;           // ktiles 8..15 (rel)
        *(uint32_t*)(smem + SM_F_LO + base)             = pack_bf2n(hlx, hly);
        *(uint32_t*)(smem + SM_F_LO + 8 * KTS + base)   = pack_bf2n(rlx, rly);
    }
    __syncthreads();

    // ---- MMA: warps 0-7, each owns m-tile = warp (16 nodes), full N=40, K=128 ----
    float lg[2][10];      // post-softmax-input logits: [rowhalf][nt*2+p]
    float lseA = 0.f, lseB = 0.f;
    if (warp < 8) {
        float acc[5][4];
        #pragma unroll
        for (int nt = 0; nt < 5; ++nt)
            #pragma unroll
            for (int p = 0; p < 4; ++p) acc[nt][p] = 0.f;

        const char* fh = smem + SM_F_HI + (warp * 2) * 128 + lane * 4;
        const char* fl = smem + SM_F_LO + (warp * 2) * 128 + lane * 4;
        const char* bh = smem + SM_B + lane * 4;
        const char* bl = bh + 10240;
        #pragma unroll 2
        for (int kt = 0; kt < 16; ++kt) {
            const uint32_t a0h = *(const uint32_t*)(fh + kt * KTS);
            const uint32_t a1h = *(const uint32_t*)(fh + kt * KTS + 128);
            const uint32_t a0l = *(const uint32_t*)(fl + kt * KTS);
            const uint32_t a1l = *(const uint32_t*)(fl + kt * KTS + 128);
            #pragma unroll
            for (int nt = 0; nt < 5; ++nt) {
                const uint32_t wh = *(const uint32_t*)(bh + (kt * 5 + nt) * 128);
                const uint32_t wl = *(const uint32_t*)(bl + (kt * 5 + nt) * 128);
                mma_bf16(acc[nt], a0h, a1h, wh);
                mma_bf16(acc[nt], a0h, a1h, wl);
                mma_bf16(acc[nt], a0l, a1l, wh);
            }
        }

        // bias + per-row log_softmax (rows: rA = 16w + lane/4, rB = rA + 8)
        #pragma unroll
        for (int nt = 0; nt < 5; ++nt) {
            const float b0 = *(const float*)(smem + SM_BIAS + (nt * 8 + (lane & 3) * 2) * 4);
            const float b1 = *(const float*)(smem + SM_BIAS + (nt * 8 + (lane & 3) * 2 + 1) * 4);
            lg[0][2 * nt]     = acc[nt][0] + b0;
            lg[0][2 * nt + 1] = acc[nt][1] + b1;
            lg[1][2 * nt]     = acc[nt][2] + b0;
            lg[1][2 * nt + 1] = acc[nt][3] + b1;
        }
        float mA = lg[0][0], mB = lg[1][0];
        #pragma unroll
        for (int i = 1; i < 10; ++i) { mA = fmaxf(mA, lg[0][i]); mB = fmaxf(mB, lg[1][i]); }
        mA = fmaxf(mA, __shfl_xor_sync(0xffffffffu, mA, 1));
        mA = fmaxf(mA, __shfl_xor_sync(0xffffffffu, mA, 2));
        mB = fmaxf(mB, __shfl_xor_sync(0xffffffffu, mB, 1));
        mB = fmaxf(mB, __shfl_xor_sync(0xffffffffu, mB, 2));
        float sA = 0.f, sB = 0.f;
        #pragma unroll
        for (int i = 0; i < 10; ++i) { sA += __expf(lg[0][i] - mA); sB += __expf(lg[1][i] - mB); }
        sA += __shfl_xor_sync(0xffffffffu, sA, 1);
        sA += __shfl_xor_sync(0xffffffffu, sA, 2);
        sB += __shfl_xor_sync(0xffffffffu, sB, 1);
        sB += __shfl_xor_sync(0xffffffffu, sB, 2);
        lseA = mA + __logf(sA);
        lseB = mB + __logf(sB);
    }
    __syncthreads();   // MMA warps done reading feat; safe to reuse as staging

    // ---- staging writes (warps 0-7): [128 nodes][stride 42] floats ----
    float* stag = reinterpret_cast<float*>(smem);
    if (warp < 8) {
        const int rA = 16 * warp + (lane >> 2);
        const int col = (lane & 3) * 2;
        #pragma unroll
        for (int nt = 0; nt < 5; ++nt) {
            float2 oA, oB;
            oA.x = lg[0][2 * nt]     - lseA;
            oA.y = lg[0][2 * nt + 1] - lseA;
            oB.x = lg[1][2 * nt]     - lseB;
            oB.y = lg[1][2 * nt + 1] - lseB;
            *(float2*)(stag + rA * 42 + nt * 8 + col)       = oA;
            *(float2*)(stag + (rA + 8) * 42 + nt * 8 + col) = oB;
        }
    }
    __syncthreads();

    // ---- coalesced output copy: 128 nodes x 40 classes ----
    {
        float* dst = out + (size_t)blockIdx.x * NODES_PER_BLOCK * NCLS;
        #pragma unroll
        for (int u = tid; u < NODES_PER_BLOCK * NCLS; u += THREADS) {
            const int node = u / NCLS, j = u - node * NCLS;
            dst[u] = stag[node * 42 + j];
        }
    }
}

extern "C" void kernel_launch(void* const* d_in, const int* in_sizes, int n_in,
                              void* d_out, int out_size) {
    const float* x  = (const float*)d_in[0];
    const void*  nb = d_in[1];
    const float* cw = (const float*)d_in[2];
    const float* cb = (const float*)d_in[3];
    const float* gw = (const float*)d_in[4];
    const float* gb = (const float*)d_in[5];
    const float* ow = (const float*)d_in[6];
    const float* ob = (const float*)d_in[7];
    float* out = (float*)d_out;

    cudaFuncSetAttribute(main_kernel, cudaFuncAttributeMaxDynamicSharedMemorySize, SMEM_BYTES);

    detect_idx_kernel<<<1, 256>>>((const unsigned int*)nb);
    cpe_kernel<<<(N_NODES / 8 * 16 + 255) / 256, 256>>>((const float4*)x, cw, cb);
    fuse_w_kernel<<<(2 * C * NCLS + NCLS + 127) / 128, 128>>>(gw, gb, ow, ob);
    main_kernel<<<N_NODES / NODES_PER_BLOCK, THREADS, SMEM_BYTES>>>(nb, out);
}